// round 14
// baseline (speedup 1.0000x reference)
#include <cuda_runtime.h>
#include <cuda_fp16.h>
#include <cstdint>

// Problem shape (fixed by dataset)
static constexpr int B_DIM   = 32768;
static constexpr int IN_DIM  = 64;
static constexpr int C_DIM   = 4096;

static constexpr int TM = 64;    // M tile per iteration
static constexpr int M_SUB = 4;  // M iterations per CTA (w tile reused 4x)
static constexpr int TN = 128;   // N tile per CTA
static constexpr int M_TILES = B_DIM / (TM * M_SUB);  // 128
static constexpr int N_TILES = C_DIM / TN;            // 32

// Preprocessed operands in device scratch (allowed: __device__ globals)
__device__ __align__(16) uint32_t x_h[B_DIM * (IN_DIM / 2)];   // fp16x2, 4 MB
__device__ __align__(16) uint32_t w_h[C_DIM * (IN_DIM / 2)];   // fp16x2, 512 KB
__device__ __align__(16) float    xsq_g[B_DIM];
__device__ __align__(16) float    wsq_g[C_DIM];

// SMEM layout (per CTA):
//   wsq   : 128 f32 (global col order)
//   xsq   : per (warp, buf) 32 f32 regions -> 8 x 128 B
//   A     : per (warp, buf) 32 rows x 144 B regions -> 8 x 4608 B (PRIVATE per warp)
//   B     : 128 rows x 144 B (column-PERMUTED), shared read-only
// Row stride 144 B (9 x 16B, odd multiple) -> conflict-free ldmatrix.
static constexpr int KP       = 72;
static constexpr int RB       = KP * 2;                 // 144 B per row
static constexpr int AREG     = 32 * RB;                // 4608 B per warp-buf region
static constexpr int OFF_WSQ  = 0;                      // 512 B
static constexpr int OFF_XSQ  = 512;                    // 8 * 128 B -> ends 1536
static constexpr int OFF_A    = 1536;                   // 8 * 4608 -> ends 38400
static constexpr int OFF_B    = 38400;                  // + 18432
static constexpr int SMEM_BYTES = OFF_B + 128 * RB;     // 56832 (x4 CTAs = 227 KB)

// ---------------- helpers ----------------
__device__ __forceinline__ uint32_t smem_u32(const void* p) {
    uint32_t a;
    asm("{ .reg .u64 t; cvta.to.shared.u64 t, %1; cvt.u32.u64 %0, t; }" : "=r"(a) : "l"(p));
    return a;
}
__device__ __forceinline__ uint32_t pack_h2(float a, float b) {
    __half2 v(__float2half_rn(a), __float2half_rn(b));
    return *reinterpret_cast<uint32_t*>(&v);
}
__device__ __forceinline__ void cpasync16(uint32_t dst, const void* src) {
    asm volatile("cp.async.cg.shared.global [%0], [%1], 16;"
                 :: "r"(dst), "l"(src) : "memory");
}
__device__ __forceinline__ void cp_commit() {
    asm volatile("cp.async.commit_group;" ::: "memory");
}
__device__ __forceinline__ void cp_wait0() {
    asm volatile("cp.async.wait_group 0;" ::: "memory");
}
__device__ __forceinline__ void ldsm_x4(uint32_t* r, uint32_t addr) {
    asm volatile("ldmatrix.sync.aligned.m8n8.x4.shared.b16 {%0,%1,%2,%3}, [%4];"
                 : "=r"(r[0]), "=r"(r[1]), "=r"(r[2]), "=r"(r[3]) : "r"(addr));
}
__device__ __forceinline__ void mma16816(float* c, const uint32_t* a, const uint32_t* b) {
    asm volatile(
        "mma.sync.aligned.m16n8k16.row.col.f32.f16.f16.f32 "
        "{%0,%1,%2,%3}, {%4,%5,%6,%7}, {%8,%9}, {%0,%1,%2,%3};"
        : "+f"(c[0]), "+f"(c[1]), "+f"(c[2]), "+f"(c[3])
        : "r"(a[0]), "r"(a[1]), "r"(a[2]), "r"(a[3]), "r"(b[0]), "r"(b[1]));
}
__device__ __forceinline__ void stg128_cs(float* p, float4 v) {
    asm volatile("st.global.cs.v4.f32 [%0], {%1,%2,%3,%4};"
                 :: "l"(p), "f"(v.x), "f"(v.y), "f"(v.z), "f"(v.w) : "memory");
}

// ---------------- pre-pass: f32 -> fp16 + squared norms ----------------
__global__ void __launch_bounds__(256)
prep_kernel(const float* __restrict__ x, const float* __restrict__ w) {
    const int bid  = blockIdx.x;
    const int tid  = threadIdx.x;
    const int lane = tid & 31;

    const bool is_x = (bid < 256);
    const size_t r0 = is_x ? (size_t)bid * 128 : (size_t)(bid - 256) * 128;
    const float4* src = reinterpret_cast<const float4*>((is_x ? x : w) + r0 * IN_DIM);
    uint32_t* dst_h  = (is_x ? x_h : w_h);
    float*    dst_sq = (is_x ? xsq_g : wsq_g);

#pragma unroll
    for (int j = 0; j < 8; j++) {
        int idx4 = j * 256 + tid;
        float4 v = src[idx4];
        int row = idx4 >> 4;
        int c4  = idx4 & 15;

        *reinterpret_cast<uint2*>(dst_h + (r0 + row) * 32 + c4 * 2) =
            make_uint2(pack_h2(v.x, v.y), pack_h2(v.z, v.w));

        float p = v.x * v.x + v.y * v.y + v.z * v.z + v.w * v.w;
        p += __shfl_xor_sync(0xFFFFFFFFu, p, 8);
        p += __shfl_xor_sync(0xFFFFFFFFu, p, 4);
        p += __shfl_xor_sync(0xFFFFFFFFu, p, 2);
        p += __shfl_xor_sync(0xFFFFFFFFu, p, 1);
        if ((lane & 15) == 0) dst_sq[r0 + row] = p;
    }
}

// ---------------- main kernel: 128 threads, 4 CTAs/SM, free-running warps ----
__global__ void __launch_bounds__(128, 4)
rbf_logits_kernel(float* __restrict__ out) {
    extern __shared__ char smem[];
    const uint32_t sb = smem_u32(smem);

    const int tid  = threadIdx.x;
    const int wid  = tid >> 5;
    const int lane = tid & 31;

    const int n_tile = blockIdx.x & (N_TILES - 1);   // consecutive CTAs share x tiles
    const int m_tile = blockIdx.x >> 5;              // N_TILES == 32
    const int n0 = n_tile * TN;

    // Warp tiling: 4 warps = 2 (M) x 2 (N); warp tile = 32 x 64
    const int m_warp = (wid >> 1) * 32;
    const int n_warp = (wid & 1) * 64;

    // Per-warp private A/xsq region offsets (buf p): region index wid*2+p
    auto a_region   = [&](int p) { return (uint32_t)(OFF_A   + (wid * 2 + p) * AREG); };
    auto xsq_region = [&](int p) { return (uint32_t)(OFF_XSQ + (wid * 2 + p) * 128);  };

    // Per-warp async loader of its own 32 A rows + its xsq slice.
    // Chunk mapping: idx = c*32+lane -> row idx>>3, chunk idx&7: lanes cover
    // 512 B contiguous global per instruction (4 lines) -> full coalescing.
    auto load_A_warp = [&](int m0, int p) {
        const char* srcb = reinterpret_cast<const char*>(x_h) +
                           ((size_t)m0 + m_warp) * 128;
        const uint32_t areg = sb + a_region(p);
#pragma unroll
        for (int c = 0; c < 8; c++) {
            int idx = c * 32 + lane;
            int row = idx >> 3;
            int c16 = idx & 7;
            cpasync16(areg + (uint32_t)(row * RB + c16 * 16),
                      srcb + (size_t)row * 128 + c16 * 16);
        }
        if (lane < 8)
            cpasync16(sb + xsq_region(p) + (uint32_t)lane * 16,
                      xsq_g + m0 + m_warp + lane * 4);
    };

    // ---- Prologue: B tile (PERMUTED rows) + wsq (block-wide) + warp A0 ----
    // Global col g -> tile row (g&0x70) | ((g&1)<<3) | ((g>>1)&7): interleaves two
    // adjacent n8 fragments so epilogue lanes own 4 consecutive global columns.
    {
        const char* srcb = reinterpret_cast<const char*>(w_h) + (size_t)n0 * 128;
#pragma unroll
        for (int j = 0; j < 8; j++) {
            int idx = j * 128 + tid;       // 0..1023
            int row = idx >> 3;
            int c16 = idx & 7;
            int trow = (row & 0x70) | ((row & 1) << 3) | ((row >> 1) & 7);
            cpasync16(sb + OFF_B + (uint32_t)(trow * RB + c16 * 16),
                      srcb + (size_t)row * 128 + c16 * 16);
        }
        if (tid < 32)
            cpasync16(sb + OFF_WSQ + (uint32_t)tid * 16, wsq_g + n0 + tid * 4);
        load_A_warp(m_tile * M_SUB * TM, 0);
        cp_commit();
        cp_wait0();
        __syncthreads();    // publish B/wsq once; no block barriers after this
    }

    // A (row-major, m16k16 tiles, region-local rows 0..31):
    // lane i -> row (i&15), k-half (i>>4)*8
    const uint32_t a_lane_off = (uint32_t)(lane & 15) * RB + ((lane >> 4) * 8) * 2;
    // B ([n][k] row-major, NON-trans): mma B frag wants lane l -> (n=l>>2, k=(l&3)*2)
    const uint32_t b_addr = sb + OFF_B +
        (uint32_t)(n_warp + ((lane >> 4) << 3) + (lane & 7)) * RB +
        (((lane >> 3) & 1) * 8) * 2;

    float* wsq = reinterpret_cast<float*>(smem + OFF_WSQ);
    const int q  = lane & 3;
    const int rl = lane >> 2;

#pragma unroll 1
    for (int sub = 0; sub < M_SUB; sub++) {
        const int p_buf = sub & 1;
        const int m0 = (m_tile * M_SUB + sub) * TM;

        if (sub > 0) {       // wait for this warp's own prefetch into buf p
            cp_wait0();
            __syncwarp();
        }

        const uint32_t a_addr0 = sb + a_region(p_buf) + a_lane_off;
        const uint32_t a_addr1 = a_addr0 + 16u * RB;
        const float* xsq = reinterpret_cast<const float*>(smem + xsq_region(p_buf));

        float acc[2][8][4];
#pragma unroll
        for (int mt = 0; mt < 2; mt++)
#pragma unroll
            for (int nt = 0; nt < 8; nt++)
#pragma unroll
                for (int t = 0; t < 4; t++) acc[mt][nt][t] = 0.0f;

#pragma unroll
        for (int ks = 0; ks < 4; ks++) {          // K = 64 in steps of 16
            const uint32_t koff = (uint32_t)ks * 16 * 2;
            uint32_t a0[4], a1[4];
            ldsm_x4(a0, a_addr0 + koff);
            ldsm_x4(a1, a_addr1 + koff);
            uint32_t b[8][2];
#pragma unroll
            for (int pp = 0; pp < 4; pp++) {
                uint32_t r[4];
                ldsm_x4(r, b_addr + (uint32_t)pp * 16 * RB + koff);
                b[2 * pp][0] = r[0]; b[2 * pp][1] = r[1];
                b[2 * pp + 1][0] = r[2]; b[2 * pp + 1][1] = r[3];
            }
#pragma unroll
            for (int nt = 0; nt < 8; nt++) {
                mma16816(acc[0][nt], a0, b[nt]);
                mma16816(acc[1][nt], a1, b[nt]);
            }
        }

        // region-local xsq: rows 0..31 of this warp's slice
        const float xs[4] = {
            xsq[rl], xsq[rl + 8], xsq[16 + rl], xsq[16 + rl + 8],
        };

        // Prefetch next tile into the other private buffer; latency hidden
        // under this iteration's epilogue (warp-local, no barrier needed).
        if (sub + 1 < M_SUB) {
            load_A_warp(m0 + TM, 1 - p_buf);
            cp_commit();
        }

        // ---- Epilogue: logits = 2*cross - x_sq - w_sq, float4 register stores ----
        // Permutation: frag 2p col c -> global p*16+2c, frag 2p+1 -> p*16+2c+1.
        // Lane q owns frag cols 2q,2q+1 of both => global cols p*16+4q..4q+3.
#pragma unroll
        for (int mt = 0; mt < 2; mt++) {
#pragma unroll
            for (int pp = 0; pp < 4; pp++) {
                const float* a = acc[mt][2 * pp];       // even global cols
                const float* b = acc[mt][2 * pp + 1];   // odd  global cols
                const int cbase = n_warp + pp * 16 + q * 4;
                const float4 wq = *reinterpret_cast<const float4*>(wsq + cbase);

                const size_t r0 = (size_t)(m0 + m_warp + mt * 16 + rl);
                const float xs0 = xs[mt * 2], xs1 = xs[mt * 2 + 1];

                float4 v0;
                v0.x = fmaf(2.0f, a[0], -(xs0 + wq.x));
                v0.y = fmaf(2.0f, b[0], -(xs0 + wq.y));
                v0.z = fmaf(2.0f, a[1], -(xs0 + wq.z));
                v0.w = fmaf(2.0f, b[1], -(xs0 + wq.w));
                stg128_cs(out + r0 * C_DIM + (n0 + cbase), v0);

                float4 v1;
                v1.x = fmaf(2.0f, a[2], -(xs1 + wq.x));
                v1.y = fmaf(2.0f, b[2], -(xs1 + wq.y));
                v1.z = fmaf(2.0f, a[3], -(xs1 + wq.z));
                v1.w = fmaf(2.0f, b[3], -(xs1 + wq.w));
                stg128_cs(out + (r0 + 8) * C_DIM + (n0 + cbase), v1);
            }
        }
    }
}

extern "C" void kernel_launch(void* const* d_in, const int* in_sizes, int n_in,
                              void* d_out, int out_size) {
    const float* x = reinterpret_cast<const float*>(d_in[0]);
    const float* w = reinterpret_cast<const float*>(d_in[1]);
    // Defensive: identify by size (x has B*64 elements, w has C*64)
    if (n_in >= 2 && in_sizes[0] == C_DIM * IN_DIM && in_sizes[1] == B_DIM * IN_DIM) {
        const float* t = x; x = w; w = t;
    }
    float* out = reinterpret_cast<float*>(d_out);

    prep_kernel<<<288, 256>>>(x, w);

    cudaFuncSetAttribute(rbf_logits_kernel,
                         cudaFuncAttributeMaxDynamicSharedMemorySize, SMEM_BYTES);
    rbf_logits_kernel<<<M_TILES * N_TILES, 128, SMEM_BYTES>>>(out);
}

// round 15
// speedup vs baseline: 1.0992x; 1.0992x over previous
#include <cuda_runtime.h>
#include <cuda_fp16.h>
#include <cstdint>

// Problem shape (fixed by dataset)
static constexpr int B_DIM   = 32768;
static constexpr int IN_DIM  = 64;
static constexpr int C_DIM   = 4096;

static constexpr int TM = 64;    // M tile per iteration
static constexpr int M_SUB = 4;  // M iterations per CTA (w tile reused 4x)
static constexpr int TN = 128;   // N tile per CTA
static constexpr int M_TILES = B_DIM / (TM * M_SUB);  // 128
static constexpr int N_TILES = C_DIM / TN;            // 32

// Preprocessed operands in device scratch (allowed: __device__ globals)
__device__ __align__(16) uint32_t x_h[B_DIM * (IN_DIM / 2)];   // fp16x2, 4 MB
__device__ __align__(16) uint32_t w_h[C_DIM * (IN_DIM / 2)];   // fp16x2, 512 KB
__device__ __align__(16) float    xsq_g[B_DIM];
__device__ __align__(16) float    wsq_g[C_DIM];

// SMEM: A = x fp16 [64 x 64k] TRIPLE-buffered ring, B = w fp16 [128 x 64k]
// (column-PERMUTED). Row stride padded to 72 halfs (144 B = 9x16B) -> conflict-free.
static constexpr int KP       = 72;
static constexpr int RB       = KP * 2;                 // 144 B per row
static constexpr int A_BYTES  = TM * RB;                // 9216
static constexpr int OFF_WSQ  = 0;                      // 128 f32 = 512 B
static constexpr int OFF_XSQ  = 512;                    // 3 bufs x 256 B -> ends 1280
static constexpr int OFF_A    = 1536;                   // 3 x 9216 -> ends 29184
static constexpr int OFF_B    = 29184;                  // + 18432
static constexpr int SMEM_BYTES = OFF_B + 128 * RB;     // 47616 (x4 CTAs = 190 KB)

// ---------------- helpers ----------------
__device__ __forceinline__ uint32_t smem_u32(const void* p) {
    uint32_t a;
    asm("{ .reg .u64 t; cvta.to.shared.u64 t, %1; cvt.u32.u64 %0, t; }" : "=r"(a) : "l"(p));
    return a;
}
__device__ __forceinline__ uint32_t pack_h2(float a, float b) {
    __half2 v(__float2half_rn(a), __float2half_rn(b));
    return *reinterpret_cast<uint32_t*>(&v);
}
__device__ __forceinline__ void cpasync16(uint32_t dst, const void* src) {
    asm volatile("cp.async.cg.shared.global [%0], [%1], 16;"
                 :: "r"(dst), "l"(src) : "memory");
}
__device__ __forceinline__ void cp_commit() {
    asm volatile("cp.async.commit_group;" ::: "memory");
}
__device__ __forceinline__ void cp_wait0() {
    asm volatile("cp.async.wait_group 0;" ::: "memory");
}
__device__ __forceinline__ void cp_wait1() {
    asm volatile("cp.async.wait_group 1;" ::: "memory");
}
__device__ __forceinline__ void ldsm_x4(uint32_t* r, uint32_t addr) {
    asm volatile("ldmatrix.sync.aligned.m8n8.x4.shared.b16 {%0,%1,%2,%3}, [%4];"
                 : "=r"(r[0]), "=r"(r[1]), "=r"(r[2]), "=r"(r[3]) : "r"(addr));
}
__device__ __forceinline__ void mma16816(float* c, const uint32_t* a, const uint32_t* b) {
    asm volatile(
        "mma.sync.aligned.m16n8k16.row.col.f32.f16.f16.f32 "
        "{%0,%1,%2,%3}, {%4,%5,%6,%7}, {%8,%9}, {%0,%1,%2,%3};"
        : "+f"(c[0]), "+f"(c[1]), "+f"(c[2]), "+f"(c[3])
        : "r"(a[0]), "r"(a[1]), "r"(a[2]), "r"(a[3]), "r"(b[0]), "r"(b[1]));
}
__device__ __forceinline__ void stg128_cs(float* p, float4 v) {
    asm volatile("st.global.cs.v4.f32 [%0], {%1,%2,%3,%4};"
                 :: "l"(p), "f"(v.x), "f"(v.y), "f"(v.z), "f"(v.w) : "memory");
}

// ---------------- pre-pass: f32 -> fp16 + squared norms ----------------
__global__ void __launch_bounds__(256)
prep_kernel(const float* __restrict__ x, const float* __restrict__ w) {
    const int bid  = blockIdx.x;
    const int tid  = threadIdx.x;
    const int lane = tid & 31;

    const bool is_x = (bid < 256);
    const size_t r0 = is_x ? (size_t)bid * 128 : (size_t)(bid - 256) * 128;
    const float4* src = reinterpret_cast<const float4*>((is_x ? x : w) + r0 * IN_DIM);
    uint32_t* dst_h  = (is_x ? x_h : w_h);
    float*    dst_sq = (is_x ? xsq_g : wsq_g);

#pragma unroll
    for (int j = 0; j < 8; j++) {
        int idx4 = j * 256 + tid;
        float4 v = src[idx4];
        int row = idx4 >> 4;
        int c4  = idx4 & 15;

        *reinterpret_cast<uint2*>(dst_h + (r0 + row) * 32 + c4 * 2) =
            make_uint2(pack_h2(v.x, v.y), pack_h2(v.z, v.w));

        float p = v.x * v.x + v.y * v.y + v.z * v.z + v.w * v.w;
        p += __shfl_xor_sync(0xFFFFFFFFu, p, 8);
        p += __shfl_xor_sync(0xFFFFFFFFu, p, 4);
        p += __shfl_xor_sync(0xFFFFFFFFu, p, 2);
        p += __shfl_xor_sync(0xFFFFFFFFu, p, 1);
        if ((lane & 15) == 0) dst_sq[r0 + row] = p;
    }
}

// ---------------- main kernel: 128 threads, 4 CTAs/SM, depth-2 pipeline ----
__global__ void __launch_bounds__(128, 4)
rbf_logits_kernel(float* __restrict__ out) {
    extern __shared__ char smem[];
    const uint32_t sb = smem_u32(smem);

    const int tid  = threadIdx.x;
    const int wid  = tid >> 5;
    const int lane = tid & 31;

    const int n_tile = blockIdx.x & (N_TILES - 1);   // consecutive CTAs share x tiles
    const int m_tile = blockIdx.x >> 5;              // N_TILES == 32
    const int n0 = n_tile * TN;

    // block-wide async x-tile loader into ring buffer bf (0..2)
    auto load_x_async = [&](int m0, int bf) {
        const char* srcb = reinterpret_cast<const char*>(x_h) + (size_t)m0 * 128;
        const uint32_t a_off = (uint32_t)(OFF_A + bf * A_BYTES);
#pragma unroll
        for (int j = 0; j < 4; j++) {
            int idx = j * 128 + tid;       // 0..511 (64 rows x 8 chunks)
            int row = idx >> 3;
            int c16 = idx & 7;
            cpasync16(sb + a_off + (uint32_t)(row * RB + c16 * 16),
                      srcb + (size_t)row * 128 + c16 * 16);
        }
        if (tid < 16)
            cpasync16(sb + (uint32_t)(OFF_XSQ + bf * 256) + (uint32_t)tid * 16,
                      xsq_g + m0 + tid * 4);
    };

    // ---- Prologue: group0 = {B PERMUTED + wsq + A buf0}; group1 = {A buf1} ----
    // Global col g -> tile row (g&0x70) | ((g&1)<<3) | ((g>>1)&7): interleaves two
    // adjacent n8 fragments so epilogue lanes own 4 consecutive global columns.
    {
        const char* srcb = reinterpret_cast<const char*>(w_h) + (size_t)n0 * 128;
#pragma unroll
        for (int j = 0; j < 8; j++) {
            int idx = j * 128 + tid;       // 0..1023
            int row = idx >> 3;
            int c16 = idx & 7;
            int trow = (row & 0x70) | ((row & 1) << 3) | ((row >> 1) & 7);
            cpasync16(sb + OFF_B + (uint32_t)(trow * RB + c16 * 16),
                      srcb + (size_t)row * 128 + c16 * 16);
        }
        if (tid < 32)
            cpasync16(sb + OFF_WSQ + (uint32_t)tid * 16, wsq_g + n0 + tid * 4);
        load_x_async(m_tile * M_SUB * TM, 0);
        cp_commit();                                   // group for buf0 (+B)
        load_x_async(m_tile * M_SUB * TM + TM, 1);
        cp_commit();                                   // group for buf1
    }

    // ---- Warp tiling: 4 warps = 2 (M) x 2 (N); warp tile = 32 x 64 ----
    const int m_warp = (wid >> 1) * 32;
    const int n_warp = (wid & 1) * 64;

    // A (row-major, m16k16 tiles): lane i -> row (i&15), k-half (i>>4)*8
    const uint32_t a_lane_off =
        (uint32_t)(m_warp + (lane & 15)) * RB + ((lane >> 4) * 8) * 2;
    // B ([n][k] row-major, NON-trans): mma B frag wants lane l -> (n=l>>2, k=(l&3)*2)
    const uint32_t b_addr = sb + OFF_B +
        (uint32_t)(n_warp + ((lane >> 4) << 3) + (lane & 7)) * RB +
        (((lane >> 3) & 1) * 8) * 2;

    float* wsq = reinterpret_cast<float*>(smem + OFF_WSQ);
    const int q  = lane & 3;
    const int rl = lane >> 2;

#pragma unroll 1
    for (int sub = 0; sub < M_SUB; sub++) {
        const int bf = sub % 3;
        const int m0 = (m_tile * M_SUB + sub) * TM;

        // Wait for this iteration's buffer (outstanding: g_sub, g_{sub+1})
        if (sub + 1 < M_SUB) cp_wait1(); else cp_wait0();
        __syncthreads();   // publishes buf sub; proves buf sub-1 readers done

        // Refill ring slot (sub+2)%3 == (sub-1)%3 — safe after the barrier.
        if (sub + 2 < M_SUB) {
            load_x_async(m0 + 2 * TM, (sub + 2) % 3);
            cp_commit();
        }

        const uint32_t a_addr0 = sb + (uint32_t)(OFF_A + bf * A_BYTES) + a_lane_off;
        const uint32_t a_addr1 = a_addr0 + 16u * RB;
        const float* xsq = reinterpret_cast<const float*>(smem + OFF_XSQ + bf * 256);

        float acc[2][8][4];
#pragma unroll
        for (int mt = 0; mt < 2; mt++)
#pragma unroll
            for (int nt = 0; nt < 8; nt++)
#pragma unroll
                for (int t = 0; t < 4; t++) acc[mt][nt][t] = 0.0f;

#pragma unroll
        for (int ks = 0; ks < 4; ks++) {          // K = 64 in steps of 16
            const uint32_t koff = (uint32_t)ks * 16 * 2;
            uint32_t a0[4], a1[4];
            ldsm_x4(a0, a_addr0 + koff);
            ldsm_x4(a1, a_addr1 + koff);
            uint32_t b[8][2];
#pragma unroll
            for (int pp = 0; pp < 4; pp++) {
                uint32_t r[4];
                ldsm_x4(r, b_addr + (uint32_t)pp * 16 * RB + koff);
                b[2 * pp][0] = r[0]; b[2 * pp][1] = r[1];
                b[2 * pp + 1][0] = r[2]; b[2 * pp + 1][1] = r[3];
            }
#pragma unroll
            for (int nt = 0; nt < 8; nt++) {
                mma16816(acc[0][nt], a0, b[nt]);
                mma16816(acc[1][nt], a1, b[nt]);
            }
        }

        const float xs[4] = {
            xsq[m_warp % 64 +      rl],  xsq[m_warp % 64 +      rl + 8],
            xsq[m_warp % 64 + 16 + rl],  xsq[m_warp % 64 + 16 + rl + 8],
        };

        // ---- Epilogue: logits = 2*cross - x_sq - w_sq, float4 register stores ----
        // Permutation: frag 2p col c -> global p*16+2c, frag 2p+1 -> p*16+2c+1.
        // Lane q owns frag cols 2q,2q+1 of both => global cols p*16+4q..4q+3.
#pragma unroll
        for (int mt = 0; mt < 2; mt++) {
#pragma unroll
            for (int pp = 0; pp < 4; pp++) {
                const float* a = acc[mt][2 * pp];       // even global cols
                const float* b = acc[mt][2 * pp + 1];   // odd  global cols
                const int cbase = n_warp + pp * 16 + q * 4;
                const float4 wq = *reinterpret_cast<const float4*>(wsq + cbase);

                const size_t r0 = (size_t)(m0 + m_warp + mt * 16 + rl);
                const float xs0 = xs[mt * 2], xs1 = xs[mt * 2 + 1];

                float4 v0;
                v0.x = fmaf(2.0f, a[0], -(xs0 + wq.x));
                v0.y = fmaf(2.0f, b[0], -(xs0 + wq.y));
                v0.z = fmaf(2.0f, a[1], -(xs0 + wq.z));
                v0.w = fmaf(2.0f, b[1], -(xs0 + wq.w));
                stg128_cs(out + r0 * C_DIM + (n0 + cbase), v0);

                float4 v1;
                v1.x = fmaf(2.0f, a[2], -(xs1 + wq.x));
                v1.y = fmaf(2.0f, b[2], -(xs1 + wq.y));
                v1.z = fmaf(2.0f, a[3], -(xs1 + wq.z));
                v1.w = fmaf(2.0f, b[3], -(xs1 + wq.w));
                stg128_cs(out + (r0 + 8) * C_DIM + (n0 + cbase), v1);
            }
        }
    }
}

extern "C" void kernel_launch(void* const* d_in, const int* in_sizes, int n_in,
                              void* d_out, int out_size) {
    const float* x = reinterpret_cast<const float*>(d_in[0]);
    const float* w = reinterpret_cast<const float*>(d_in[1]);
    // Defensive: identify by size (x has B*64 elements, w has C*64)
    if (n_in >= 2 && in_sizes[0] == C_DIM * IN_DIM && in_sizes[1] == B_DIM * IN_DIM) {
        const float* t = x; x = w; w = t;
    }
    float* out = reinterpret_cast<float*>(d_out);

    prep_kernel<<<288, 256>>>(x, w);

    cudaFuncSetAttribute(rbf_logits_kernel,
                         cudaFuncAttributeMaxDynamicSharedMemorySize, SMEM_BYTES);
    rbf_logits_kernel<<<M_TILES * N_TILES, 128, SMEM_BYTES>>>(out);
}